// round 1
// baseline (speedup 1.0000x reference)
#include <cuda_runtime.h>
#include <cstdint>

// Problem constants
#define BNtok 65536      // B*N tokens
#define Dh    512        // model dim
#define Scnt  2          // slices
#define Kcb   1024       // codes per codebook
#define DSc   256        // slice dim
#define TM    128        // tokens per block tile
#define TN    128        // codes per w-tile
#define KC    64         // d-chunk depth

#define XT_PITCH 132     // padded pitch for transposed tiles

// scratch (no cudaMalloc allowed)
__device__ float  g_wsq[Scnt * Kcb];
__device__ int    g_ids[Scnt * BNtok];
__device__ double g_loss;

// ---------------------------------------------------------------------------
// prep: codebook squared norms + zero loss accumulator
// ---------------------------------------------------------------------------
__global__ void prep_kernel(const float* __restrict__ W) {
    int idx = blockIdx.x * blockDim.x + threadIdx.x;
    if (idx == 0) g_loss = 0.0;
    if (idx < Scnt * Kcb) {
        const float* w = W + (size_t)idx * DSc;
        float s = 0.f;
        #pragma unroll 8
        for (int d = 0; d < DSc; d++) s += w[d] * w[d];
        g_wsq[idx] = s;
    }
}

// ---------------------------------------------------------------------------
// main: fused GEMM + argmin per (token, slice)
// dist = (x_sq + w_sq) - 2*dot   (fp32, matching reference quantization)
// argmin with first-index tie-break (matches jnp.argmin)
// ---------------------------------------------------------------------------
extern __shared__ float smem_f[];

__global__ void __launch_bounds__(256, 1)
argmin_kernel(const float* __restrict__ h, const float* __restrict__ W) {
    const int s  = blockIdx.y;
    const int m0 = blockIdx.x * TM;

    float* xT   = smem_f;                       // [256][XT_PITCH] transposed x
    float* wT   = xT + 256 * XT_PITCH;          // [KC][XT_PITCH]  transposed w chunk
    float* sxsq = wT + KC * XT_PITCH;           // [TM]
    float* swsq = sxsq + TM;                    // [TN]
    // reduction arrays alias wT after main loop
    float* bestS = wT;                          // [TM][17]
    int*   bidS  = (int*)(wT + TM * 17);        // [TM][17]

    const int tid = threadIdx.x;
    const int tx  = tid & 15;
    const int ty  = tid >> 4;

    // ---- load x tile [TM][DSc], store transposed xT[d][m] ----
    const float4* h4 = (const float4*)h;
    #pragma unroll 4
    for (int it = 0; it < 32; it++) {
        int fid = it * 256 + tid;
        int r   = fid >> 6;        // token row 0..127
        int c4  = fid & 63;        // float4 col 0..63
        float4 v = h4[(size_t)(m0 + r) * (Dh / 4) + s * (DSc / 4) + c4];
        float* p = xT + (c4 * 4) * XT_PITCH + r;
        p[0 * XT_PITCH] = v.x;
        p[1 * XT_PITCH] = v.y;
        p[2 * XT_PITCH] = v.z;
        p[3 * XT_PITCH] = v.w;
    }
    __syncthreads();

    // ---- x squared norms ----
    if (tid < TM) {
        float acc = 0.f;
        #pragma unroll 8
        for (int d = 0; d < DSc; d++) {
            float v = xT[d * XT_PITCH + tid];
            acc += v * v;
        }
        sxsq[tid] = acc;
    }

    float best[8];
    int   bid[8];
    #pragma unroll
    for (int i = 0; i < 8; i++) { best[i] = __int_as_float(0x7f800000); bid[i] = 0; }

    const float4* W4 = (const float4*)W;

    for (int wt = 0; wt < Kcb / TN; wt++) {
        const int k0 = wt * TN;
        __syncthreads();   // protect swsq/wT from previous iteration readers
        if (tid < TN) swsq[tid] = g_wsq[s * Kcb + k0 + tid];

        float acc[8][8];
        #pragma unroll
        for (int i = 0; i < 8; i++)
            #pragma unroll
            for (int j = 0; j < 8; j++) acc[i][j] = 0.f;

        for (int c = 0; c < DSc / KC; c++) {
            if (c > 0) __syncthreads();
            // load w chunk: codes [k0, k0+TN), dims [c*KC, c*KC+KC), transposed
            #pragma unroll 4
            for (int it = 0; it < 8; it++) {
                int fid = it * 256 + tid;
                int k   = fid >> 4;     // code 0..127
                int c4  = fid & 15;     // float4 within chunk 0..15
                float4 v = W4[((size_t)s * Kcb + k0 + k) * (DSc / 4) + c * (KC / 4) + c4];
                float* p = wT + (c4 * 4) * XT_PITCH + k;
                p[0 * XT_PITCH] = v.x;
                p[1 * XT_PITCH] = v.y;
                p[2 * XT_PITCH] = v.z;
                p[3 * XT_PITCH] = v.w;
            }
            __syncthreads();

            #pragma unroll 4
            for (int kk = 0; kk < KC; kk++) {
                const float* xrow = xT + (c * KC + kk) * XT_PITCH + ty * 8;
                const float* wrow = wT + kk * XT_PITCH + tx * 8;
                float4 a0 = *(const float4*)(xrow);
                float4 a1 = *(const float4*)(xrow + 4);
                float4 b0 = *(const float4*)(wrow);
                float4 b1 = *(const float4*)(wrow + 4);
                float av[8] = {a0.x, a0.y, a0.z, a0.w, a1.x, a1.y, a1.z, a1.w};
                float bv[8] = {b0.x, b0.y, b0.z, b0.w, b1.x, b1.y, b1.z, b1.w};
                #pragma unroll
                for (int i = 0; i < 8; i++)
                    #pragma unroll
                    for (int j = 0; j < 8; j++)
                        acc[i][j] = fmaf(av[i], bv[j], acc[i][j]);
            }
        }

        // epilogue: dist & running argmin (ascending k preserves first-index ties)
        float xsq_i[8];
        #pragma unroll
        for (int i = 0; i < 8; i++) xsq_i[i] = sxsq[ty * 8 + i];
        #pragma unroll
        for (int j = 0; j < 8; j++) {
            int   k   = k0 + tx * 8 + j;
            float wsq = swsq[tx * 8 + j];
            #pragma unroll
            for (int i = 0; i < 8; i++) {
                float dist = (xsq_i[i] + wsq) - 2.0f * acc[i][j];
                if (dist < best[i]) { best[i] = dist; bid[i] = k; }
            }
        }
    }

    __syncthreads();
    #pragma unroll
    for (int i = 0; i < 8; i++) {
        int r = ty * 8 + i;
        bestS[r * 17 + tx] = best[i];
        bidS[r * 17 + tx]  = bid[i];
    }
    __syncthreads();

    if (tid < TM) {
        float bb = __int_as_float(0x7f800000);
        int   bi = 0x7fffffff;
        for (int t = 0; t < 16; t++) {
            float v = bestS[tid * 17 + t];
            int   k = bidS[tid * 17 + t];
            if (v < bb || (v == bb && k < bi)) { bb = v; bi = k; }
        }
        g_ids[s * BNtok + m0 + tid] = bi;
    }
}

// ---------------------------------------------------------------------------
// gather: z = W[s, id], loss partials, packed ids
// one warp per (token, slice); 4 tokens per 256-thread block
// ---------------------------------------------------------------------------
__global__ void gather_kernel(const float* __restrict__ h,
                              const float* __restrict__ W,
                              float* __restrict__ out, int write_ids) {
    __shared__ float bsum;
    const int warp = threadIdx.x >> 5;
    const int lane = threadIdx.x & 31;
    const int m = blockIdx.x * 4 + (warp >> 1);
    const int s = warp & 1;

    const int id = g_ids[s * BNtok + m];
    const float4* wrow = (const float4*)(W + ((size_t)s * Kcb + id) * DSc);
    const float4* hrow = (const float4*)(h + (size_t)m * Dh + s * DSc);
    float4*       orow = (float4*)(out + (size_t)m * Dh + s * DSc);

    if (threadIdx.x == 0) bsum = 0.f;
    __syncthreads();

    float lsum = 0.f;
    #pragma unroll
    for (int it = 0; it < 2; it++) {
        int c = lane + it * 32;
        float4 wv = wrow[c];
        float4 hv = hrow[c];
        orow[c] = wv;   // z == z_q (straight-through is identity in value)
        float dx = wv.x - hv.x, dy = wv.y - hv.y;
        float dz = wv.z - hv.z, dw = wv.w - hv.w;
        lsum += dx * dx + dy * dy + dz * dz + dw * dw;
    }
    #pragma unroll
    for (int o = 16; o > 0; o >>= 1)
        lsum += __shfl_down_sync(0xffffffff, lsum, o);
    if (lane == 0) atomicAdd(&bsum, lsum);
    __syncthreads();
    if (threadIdx.x == 0) atomicAdd(&g_loss, (double)bsum);

    if (write_ids && threadIdx.x < 4) {
        int mm = blockIdx.x * 4 + threadIdx.x;
        int packed = g_ids[mm] + Kcb * g_ids[BNtok + mm];
        out[(size_t)BNtok * Dh + mm] = (float)packed;
    }
}

// ---------------------------------------------------------------------------
// finalize: vq_total = 1.25 * sum / (BN*DS)
// ---------------------------------------------------------------------------
__global__ void finalize_kernel(float* __restrict__ out) {
    out[(size_t)BNtok * Dh + BNtok] = (float)(1.25 * g_loss / 16777216.0);
}

// ---------------------------------------------------------------------------
extern "C" void kernel_launch(void* const* d_in, const int* in_sizes, int n_in,
                              void* d_out, int out_size) {
    const float* h = (const float*)d_in[0];
    const float* W = (const float*)d_in[1];
    // defensive: identify by size (h = 33554432, W = 524288)
    if (n_in >= 2 && in_sizes[0] == Scnt * Kcb * DSc) {
        const float* t = h; h = W; W = t;
    }
    float* out = (float*)d_out;

    const int smem_bytes = (256 * XT_PITCH + KC * XT_PITCH + TM + TN) * (int)sizeof(float);
    cudaFuncSetAttribute(argmin_kernel,
                         cudaFuncAttributeMaxDynamicSharedMemorySize, smem_bytes);

    prep_kernel<<<8, 256>>>(W);

    dim3 grid(BNtok / TM, Scnt);
    argmin_kernel<<<grid, 256, smem_bytes>>>(h, W);

    int write_ids = (out_size >= BNtok * Dh + BNtok) ? 1 : 0;
    gather_kernel<<<BNtok / 4, 256>>>(h, W, out, write_ids);

    if (out_size >= BNtok * Dh + BNtok + 1)
        finalize_kernel<<<1, 1>>>(out);
}

// round 4
// speedup vs baseline: 3.8347x; 3.8347x over previous
#include <cuda_runtime.h>
#include <cuda_bf16.h>
#include <cstdint>

#define BNtok 65536
#define Dh    512
#define Kcb   1024
#define DSc   256

#define MARGIN 1e-3f
#define CAP    16

// ---------------- device scratch (no cudaMalloc allowed) -------------------
// bf16 W, swizzled: [s][tile(8)][chunk(4)][128 codes x 64 bf16] (16KB units)
__device__ __align__(16) uint8_t g_whi[(size_t)2 * 8 * 65536];
__device__ float  g_wsq[2 * Kcb];
__device__ int    g_ids[2 * BNtok];
__device__ double g_loss;

// ---------------- helpers --------------------------------------------------
#define SWZ(o) ((o) ^ (((o) >> 3) & 0x70))

static __device__ __forceinline__ uint32_t smem_u32(const void* p) {
    uint32_t a;
    asm("{ .reg .u64 t; cvta.to.shared.u64 t, %1; cvt.u32.u64 %0, t; }" : "=r"(a) : "l"(p));
    return a;
}

#define LDSM_X4(r0, r1, r2, r3, addr) \
    asm volatile("ldmatrix.sync.aligned.m8n8.x4.shared.b16 {%0,%1,%2,%3}, [%4];" \
        : "=r"(r0), "=r"(r1), "=r"(r2), "=r"(r3) : "r"(addr))

#define MMA16816(d, a0, a1, a2, a3, b0, b1) \
    asm volatile("mma.sync.aligned.m16n8k16.row.col.f32.bf16.bf16.f32 " \
        "{%0,%1,%2,%3}, {%4,%5,%6,%7}, {%8,%9}, {%0,%1,%2,%3};" \
        : "+f"((d)[0]), "+f"((d)[1]), "+f"((d)[2]), "+f"((d)[3]) \
        : "r"(a0), "r"(a1), "r"(a2), "r"(a3), "r"(b0), "r"(b1))

#define CP_ASYNC16(saddr, gptr) \
    asm volatile("cp.async.cg.shared.global [%0], [%1], 16;" :: "r"(saddr), "l"(gptr))
#define CP_COMMIT() asm volatile("cp.async.commit_group;" ::: "memory")

static __device__ __forceinline__ uint32_t pack2bf(float a, float b) {
    uint32_t lo = __bfloat16_as_ushort(__float2bfloat16_rn(a));
    uint32_t hi = __bfloat16_as_ushort(__float2bfloat16_rn(b));
    return lo | (hi << 16);
}

// ---------------- smem layout (bytes) --------------------------------------
#define XOFF   0         // A: 4 chunks x [128 tok x 64 bf16] = 65536
#define BOFF   65536     // B: 2 stages x 65536
#define WSQO   196608    // 1024 floats = 4096
#define CANDO  200704    // 128 x CAP u16 = 4096
#define SCNTO  204800    // 128 ints = 512
#define SMEM_SZ 205312

// ---------------------------------------------------------------------------
// prep: W -> bf16 swizzled tiles + w_sq + zero loss.  grid 256 x 256
// ---------------------------------------------------------------------------
__global__ void prep_kernel(const float* __restrict__ W) {
    int gid = blockIdx.x * 256 + threadIdx.x;
    if (gid == 0) g_loss = 0.0;
    const float4* W4 = (const float4*)W;

    #pragma unroll
    for (int r = 0; r < 2; r++) {
        int fid  = gid * 2 + r;            // 0..131071
        int code = fid >> 6;               // 0..2047 (s*1024 + kk)
        int q    = fid & 63;               // float4 idx in 256 dims
        float4 v = W4[(size_t)code * 64 + q];
        int kk    = code & 1023;
        int s     = code >> 10;
        int tile  = kk >> 7;               // 0..7
        int k     = kk & 127;
        int chunk = q >> 4;
        int qq    = q & 15;
        uint8_t* base = g_whi + ((size_t)(((s * 8 + tile) * 4) + chunk)) * 16384;
        uint32_t off = SWZ((uint32_t)(k * 128 + qq * 8));
        *(uint2*)(base + off) = make_uint2(pack2bf(v.x, v.y), pack2bf(v.z, v.w));
    }

    int code = gid >> 5;
    int lane = gid & 31;
    float s = 0.f;
    #pragma unroll
    for (int r = 0; r < 2; r++) {
        float4 v = W4[(size_t)code * 64 + lane + r * 32];
        s += v.x * v.x + v.y * v.y + v.z * v.z + v.w * v.w;
    }
    #pragma unroll
    for (int o = 16; o > 0; o >>= 1) s += __shfl_xor_sync(0xffffffffu, s, o);
    if (lane == 0) g_wsq[code] = s;
}

// ---------------------------------------------------------------------------
// fused: bf16 mma.sync scoring + candidate capture + exact rescore + z + loss
// grid = 1024 (512 token-tiles x 2 slices), 256 threads (8 warps)
// warp w owns tokens [w*16, w*16+16)
// ---------------------------------------------------------------------------
__global__ void __launch_bounds__(256, 1)
vq_kernel(const float* __restrict__ h, const float* __restrict__ W,
          float* __restrict__ out) {
    extern __shared__ __align__(1024) uint8_t smem[];
    const uint32_t sb = smem_u32(smem);

    const int tid = threadIdx.x;
    const int wid = tid >> 5;
    const int lid = tid & 31;
    const int g   = lid >> 2;
    const int t   = lid & 3;
    const int blk = blockIdx.x;
    const int s   = blk >> 9;
    const int m0  = (blk & 511) * 128;

    float*    swsq  = (float*)(smem + WSQO);
    uint16_t* candp = (uint16_t*)(smem + CANDO);
    int*      scnt  = (int*)(smem + SCNTO);

    if (tid < 128) scnt[tid] = 0;
    #pragma unroll
    for (int i = 0; i < 4; i++) swsq[i * 256 + tid] = g_wsq[s * Kcb + i * 256 + tid];

    // ---- x tile -> bf16, 4 swizzled chunks [128 x 64] ----
    const float4* h4 = (const float4*)h;
    #pragma unroll 4
    for (int it = 0; it < 32; it++) {
        int fid = it * 256 + tid;
        int r   = fid >> 6;
        int c4  = fid & 63;
        float4 v = h4[(size_t)(m0 + r) * (Dh / 4) + s * (DSc / 4) + c4];
        int chunk = c4 >> 4, qq = c4 & 15;
        uint32_t off = XOFF + chunk * 16384 + SWZ((uint32_t)(r * 128 + qq * 8));
        *(uint2*)(smem + off) = make_uint2(pack2bf(v.x, v.y), pack2bf(v.z, v.w));
    }

    // ---- ldmatrix lane addressing ----
    const int arow = wid * 16 + (lid & 7) + ((lid & 8) ? 8 : 0);
    const uint32_t aBase = sb + XOFF + (uint32_t)arow * 128;
    const uint32_t akhi  = (lid & 16) ? 16u : 0u;
    const uint32_t sxA   = (uint32_t)(arow & 7) << 4;
    const int brow = (lid & 7) + ((lid & 16) ? 8 : 0);
    const uint32_t bkhi  = (lid & 8) ? 16u : 0u;
    const uint32_t sxB   = (uint32_t)(brow & 7) << 4;
    const uint32_t brOff = (uint32_t)brow * 128;

    // ---- prefetch B tiles 0,1 ----
    const uint8_t* wsrc = g_whi + (size_t)s * 8 * 65536;
    {
        #pragma unroll
        for (int p = 0; p < 2; p++) {
            const uint8_t* src = wsrc + (size_t)p * 65536 + tid * 16;
            uint32_t dst = sb + BOFF + p * 65536 + tid * 16;
            #pragma unroll
            for (int i = 0; i < 16; i++) CP_ASYNC16(dst + i * 4096, src + i * 4096);
            CP_COMMIT();
        }
    }

    float vminA = 1e30f, vminB = 1e30f;
    const int tokA = wid * 16 + g;
    const int tokB = tokA + 8;

    for (int tile = 0; tile < 8; tile++) {
        if (tile < 7) asm volatile("cp.async.wait_group 1;" ::: "memory");
        else          asm volatile("cp.async.wait_group 0;" ::: "memory");
        __syncthreads();

        // ---- mma accumulation: 16 tokens x 128 codes x 256 dims ----
        float acc[16][4];
        #pragma unroll
        for (int n = 0; n < 16; n++)
            #pragma unroll
            for (int e = 0; e < 4; e++) acc[n][e] = 0.f;

        const uint32_t bbase = sb + BOFF + (tile & 1) * 65536;
        #pragma unroll
        for (int kc = 0; kc < 4; kc++) {
            #pragma unroll
            for (int kk = 0; kk < 4; kk++) {
                uint32_t a0, a1, a2, a3;
                LDSM_X4(a0, a1, a2, a3,
                        aBase + kc * 16384 + (((uint32_t)(kk * 32) + akhi) ^ sxA));
                uint32_t bq[32];
                const uint32_t kb = ((uint32_t)(kk * 32) + bkhi) ^ sxB;
                #pragma unroll
                for (int n8 = 0; n8 < 8; n8++)
                    LDSM_X4(bq[n8 * 4], bq[n8 * 4 + 1], bq[n8 * 4 + 2], bq[n8 * 4 + 3],
                            bbase + kc * 16384 + n8 * 2048 + brOff + kb);
                #pragma unroll
                for (int nt = 0; nt < 16; nt++)
                    MMA16816(acc[nt], a0, a1, a2, a3, bq[nt * 2], bq[nt * 2 + 1]);
            }
        }

        // ---- epilogue: scores, running min, candidate capture ----
        float mnA = 1e30f, mnB = 1e30f;
        const int kbase = tile * 128 + 2 * t;
        #pragma unroll
        for (int nt = 0; nt < 16; nt++) {
            float2 wv = *(const float2*)(smem + WSQO + (size_t)(kbase + nt * 8) * 4);
            acc[nt][0] = fmaf(-2.f, acc[nt][0], wv.x);
            acc[nt][1] = fmaf(-2.f, acc[nt][1], wv.y);
            acc[nt][2] = fmaf(-2.f, acc[nt][2], wv.x);
            acc[nt][3] = fmaf(-2.f, acc[nt][3], wv.y);
            mnA = fminf(mnA, fminf(acc[nt][0], acc[nt][1]));
            mnB = fminf(mnB, fminf(acc[nt][2], acc[nt][3]));
        }
        mnA = fminf(mnA, __shfl_xor_sync(0xffffffffu, mnA, 1));
        mnA = fminf(mnA, __shfl_xor_sync(0xffffffffu, mnA, 2));
        mnB = fminf(mnB, __shfl_xor_sync(0xffffffffu, mnB, 1));
        mnB = fminf(mnB, __shfl_xor_sync(0xffffffffu, mnB, 2));
        vminA = fminf(vminA, mnA);
        vminB = fminf(vminB, mnB);
        const float thA = vminA + MARGIN;
        const float thB = vminB + MARGIN;
        #pragma unroll
        for (int nt = 0; nt < 16; nt++) {
            int k0 = kbase + nt * 8;
            if (acc[nt][0] < thA) { int sl = atomicAdd(&scnt[tokA], 1); if (sl < CAP) candp[tokA * CAP + sl] = (uint16_t)k0; }
            if (acc[nt][1] < thA) { int sl = atomicAdd(&scnt[tokA], 1); if (sl < CAP) candp[tokA * CAP + sl] = (uint16_t)(k0 + 1); }
            if (acc[nt][2] < thB) { int sl = atomicAdd(&scnt[tokB], 1); if (sl < CAP) candp[tokB * CAP + sl] = (uint16_t)k0; }
            if (acc[nt][3] < thB) { int sl = atomicAdd(&scnt[tokB], 1); if (sl < CAP) candp[tokB * CAP + sl] = (uint16_t)(k0 + 1); }
        }

        __syncthreads();
        if (tile + 2 < 8) {
            const uint8_t* src = wsrc + (size_t)(tile + 2) * 65536 + tid * 16;
            uint32_t dst = sb + BOFF + (tile & 1) * 65536 + tid * 16;
            #pragma unroll
            for (int i = 0; i < 16; i++) CP_ASYNC16(dst + i * 4096, src + i * 4096);
            CP_COMMIT();
        }
    }

    // ---- exact rescore + z write + loss (warp owns its 16 tokens) ----
    const float4* W4 = (const float4*)W;
    float4* o4 = (float4*)out;
    float lsum = 0.f;

    for (int tl = 0; tl < 16; tl++) {
        const int tok = wid * 16 + tl;
        const int m   = m0 + tok;
        const int tc  = scnt[tok];

        const float4* xr = h4 + (size_t)m * (Dh / 4) + s * (DSc / 4);
        float4 xa = xr[lid * 2];
        float4 xb = xr[lid * 2 + 1];
        float xs = xa.x * xa.x + xa.y * xa.y + xa.z * xa.z + xa.w * xa.w
                 + xb.x * xb.x + xb.y * xb.y + xb.z * xb.z + xb.w * xb.w;
        #pragma unroll
        for (int o = 16; o > 0; o >>= 1) xs += __shfl_xor_sync(0xffffffffu, xs, o);

        const int ncand = (tc > CAP) ? Kcb : tc;
        float best = 1e30f;
        int   bid  = 0x7fffffff;
        for (int j = 0; j < ncand; j++) {
            const int k = (tc > CAP) ? j : (int)candp[tok * CAP + j];
            const float4* wr = W4 + ((size_t)s * Kcb + k) * (DSc / 4);
            float4 wa = wr[lid * 2];
            float4 wb = wr[lid * 2 + 1];
            float dp = xa.x * wa.x + xa.y * wa.y + xa.z * wa.z + xa.w * wa.w
                     + xb.x * wb.x + xb.y * wb.y + xb.z * wb.z + xb.w * wb.w;
            #pragma unroll
            for (int o = 16; o > 0; o >>= 1) dp += __shfl_xor_sync(0xffffffffu, dp, o);
            float dist = (xs + swsq[k]) - 2.0f * dp;
            if (dist < best || (dist == best && k < bid)) { best = dist; bid = k; }
        }

        if (lid == 0) {
            g_ids[s * BNtok + m] = bid;
            lsum += best;
        }
        const float4* wrw = W4 + ((size_t)s * Kcb + bid) * (DSc / 4);
        float4* orow = o4 + (size_t)m * (Dh / 4) + s * (DSc / 4);
        orow[lid * 2]     = wrw[lid * 2];
        orow[lid * 2 + 1] = wrw[lid * 2 + 1];
    }
    if (lid == 0) atomicAdd(&g_loss, (double)lsum);
}

// ---------------------------------------------------------------------------
__global__ void pack_kernel(float* __restrict__ out) {
    int m = blockIdx.x * 256 + threadIdx.x;
    out[(size_t)BNtok * Dh + m] = (float)(g_ids[m] + Kcb * g_ids[BNtok + m]);
}

__global__ void finalize_kernel(float* __restrict__ out) {
    out[(size_t)BNtok * Dh + BNtok] = (float)(1.25 * g_loss / 16777216.0);
}

// ---------------------------------------------------------------------------
extern "C" void kernel_launch(void* const* d_in, const int* in_sizes, int n_in,
                              void* d_out, int out_size) {
    const float* h = (const float*)d_in[0];
    const float* W = (const float*)d_in[1];
    if (n_in >= 2 && in_sizes[0] == 2 * Kcb * DSc) {  // defensive swap
        const float* tp = h; h = W; W = tp;
    }
    float* out = (float*)d_out;

    cudaFuncSetAttribute(vq_kernel, cudaFuncAttributeMaxDynamicSharedMemorySize, SMEM_SZ);

    prep_kernel<<<256, 256>>>(W);
    vq_kernel<<<1024, 256, SMEM_SZ>>>(h, W, out);

    if (out_size >= BNtok * Dh + BNtok)
        pack_kernel<<<BNtok / 256, 256>>>(out);
    if (out_size >= BNtok * Dh + BNtok + 1)
        finalize_kernel<<<1, 1>>>(out);
}